// round 7
// baseline (speedup 1.0000x reference)
#include <cuda_runtime.h>
#include <cuda_bf16.h>
#include <cstdint>

// Shapes: enc [8,512,256], dec [8,640,128], W_enc [640,512], b_enc[640],
// W_pred [640,640], b_pred[640], W_out [1025,640], b_out[1025]
// out [8,256,128,1025] fp32
#define E_ 512
#define P_ 640
#define T_ 256
#define U_ 128

// Static scratch (no allocation)
__device__ __align__(16)  float         g_e[2048 * 640];   // [B*T, J]
__device__ __align__(16)  float         g_p[1024 * 640];   // [B*U, J]
__device__ __align__(256) __nv_bfloat16 g_w[1025 * 640];   // W_out bf16

// ---------------------------------------------------------------------------
// Kernel 0: W_out -> bf16
// ---------------------------------------------------------------------------
__global__ void convw_kernel(const float* __restrict__ w) {
    int i = blockIdx.x * 256 + threadIdx.x;
    if (i < (1025 * 640) / 4) {
        float4 v = *(const float4*)(w + (size_t)i * 4);
        *(__nv_bfloat162*)(g_w + (size_t)i * 4)     = __floats2bfloat162_rn(v.x, v.y);
        *(__nv_bfloat162*)(g_w + (size_t)i * 4 + 2) = __floats2bfloat162_rn(v.z, v.w);
    }
}

// ---------------------------------------------------------------------------
// Kernel 1: projection GEMM (fp32, exact) — unchanged (proven in R4)
// ---------------------------------------------------------------------------
__global__ void __launch_bounds__(256) proj_kernel(
    const float* __restrict__ src, const float* __restrict__ W,
    const float* __restrict__ bias, int K, int X, int which)
{
    __shared__ float As[16][132];
    __shared__ float Bs[16][132];
    float* outp = which ? g_p : g_e;

    int m0 = blockIdx.x * 128;
    int j0 = blockIdx.y * 128;
    int b  = m0 / X;
    int x0 = m0 % X;
    int tid = threadIdx.x;
    int tm = tid & 15, tn = tid >> 4;

    float acc[8][8];
#pragma unroll
    for (int i = 0; i < 8; i++)
#pragma unroll
        for (int j = 0; j < 8; j++) acc[i][j] = 0.f;

    for (int k0 = 0; k0 < K; k0 += 16) {
        {
            int kk = tid >> 5;
            int ml = (tid & 31) * 4;
            const float* s = src + ((size_t)b * K + k0 + kk) * X + x0 + ml;
            float4 v0 = *(const float4*)s;
            float4 v1 = *(const float4*)(s + (size_t)8 * X);
            *(float4*)&As[kk][ml]     = v0;
            *(float4*)&As[kk + 8][ml] = v1;
        }
        {
            int j  = tid >> 2;
            int k4 = (tid & 3) * 4;
#pragma unroll
            for (int pass = 0; pass < 2; pass++) {
                int jj = j + pass * 64;
                float4 v = *(const float4*)(W + (size_t)(j0 + jj) * K + k0 + k4);
                Bs[k4 + 0][jj] = v.x; Bs[k4 + 1][jj] = v.y;
                Bs[k4 + 2][jj] = v.z; Bs[k4 + 3][jj] = v.w;
            }
        }
        __syncthreads();
#pragma unroll
        for (int kk = 0; kk < 16; kk++) {
            float a[8], bb[8];
            *(float4*)(a)      = *(float4*)&As[kk][tm * 8];
            *(float4*)(a + 4)  = *(float4*)&As[kk][tm * 8 + 4];
            *(float4*)(bb)     = *(float4*)&Bs[kk][tn * 8];
            *(float4*)(bb + 4) = *(float4*)&Bs[kk][tn * 8 + 4];
#pragma unroll
            for (int i = 0; i < 8; i++)
#pragma unroll
                for (int j = 0; j < 8; j++) acc[i][j] += a[i] * bb[j];
        }
        __syncthreads();
    }
#pragma unroll
    for (int i = 0; i < 8; i++) {
        int m = m0 + tm * 8 + i;
        float* orow = outp + (size_t)m * 640 + j0 + tn * 8;
#pragma unroll
        for (int j = 0; j < 8; j++) orow[j] = acc[i][j] + bias[j0 + tn * 8 + j];
    }
}

// ---------------------------------------------------------------------------
// PTX helpers (mma.sync path — tcgen05 unavailable in this toolchain)
// ---------------------------------------------------------------------------
__device__ __forceinline__ uint32_t smem_u32(const void* p) {
    return (uint32_t)__cvta_generic_to_shared(p);
}
__device__ __forceinline__ void ldsm4(uint32_t* r, uint32_t addr) {
    asm volatile("ldmatrix.sync.aligned.m8n8.x4.shared.b16 {%0,%1,%2,%3}, [%4];"
                 : "=r"(r[0]), "=r"(r[1]), "=r"(r[2]), "=r"(r[3]) : "r"(addr));
}
__device__ __forceinline__ void mma16816(float* c, const uint32_t* a, const uint32_t* b) {
    asm volatile(
        "mma.sync.aligned.m16n8k16.row.col.f32.bf16.bf16.f32 "
        "{%0,%1,%2,%3}, {%4,%5,%6,%7}, {%8,%9}, {%0,%1,%2,%3};"
        : "+f"(c[0]), "+f"(c[1]), "+f"(c[2]), "+f"(c[3])
        : "r"(a[0]), "r"(a[1]), "r"(a[2]), "r"(a[3]), "r"(b[0]), "r"(b[1]));
}
__device__ __forceinline__ void cp_async16(uint32_t dst, const void* src) {
    asm volatile("cp.async.cg.shared.global [%0], [%1], 16;\n" :: "r"(dst), "l"(src));
}

// ---------------------------------------------------------------------------
// Kernel 2: fused joint + HMMA GEMM + log_softmax
// One CTA per (b,t), 256 threads (8 warps). Warp tile 64x64, CTA tile 128x256,
// 4 n-tiles. h resident in smem (pitch 648 bf16). W streamed in [256 n][32 k]
// chunks (pitch 80B, cp.async double-buffered). Output staged through a rotated
// smem buffer (aliased into W buf1); gmem stores are SCALAR (row pitch 1025
// floats -> 16B vectors would be misaligned on 3 of 4 rows).
// ---------------------------------------------------------------------------
#define HP 648                     // h pitch in bf16 (1296B rows, ldsm conflict-free)
#define WCHUNK 20480               // 256 rows * 80B
#define SM_A      0                // 128 * 1296 = 165888
#define SM_B      165888           // 2 * 20480 = 40960 (buf1 doubles as stage)
#define SM_STAGE  (SM_B + WCHUNK)  // 128*32 fp32 = 16384 (aliases buf1)
#define SM_WMAX   206848           // 4*128 fp32
#define SM_WSUM   208896           // 4*128 fp32
#define SM_RUNM   210944           // 128 fp32
#define SM_RUNS   211456           // 128 fp32
#define SMEM_TOTAL 211968

__device__ __forceinline__ void issue_chunk(uint32_t wsm, int g, int tid) {
    int nt = g / 20, kc = g - nt * 20;
    const char* src = (const char*)g_w + ((size_t)(nt * 256) * 640 + (size_t)kc * 32) * 2;
    uint32_t dst = wsm + (uint32_t)(g & 1) * WCHUNK;
#pragma unroll
    for (int it = 0; it < 4; it++) {
        int idx = it * 256 + tid;
        int row = idx >> 2, v = idx & 3;
        cp_async16(dst + row * 80 + v * 16, src + (size_t)row * 1280 + v * 16);
    }
}

__global__ void __launch_bounds__(256, 1) joint_kernel(
    const float* __restrict__ bout, float* __restrict__ out)
{
    extern __shared__ char sm[];
    __nv_bfloat16* hs = (__nv_bfloat16*)sm;
    float* stage = (float*)(sm + SM_STAGE);
    float* wmax  = (float*)(sm + SM_WMAX);
    float* wsum  = (float*)(sm + SM_WSUM);
    float* runM  = (float*)(sm + SM_RUNM);
    float* runS  = (float*)(sm + SM_RUNS);
    const uint32_t hsm = smem_u32(sm);
    const uint32_t wsm = hsm + SM_B;

    int tid  = threadIdx.x;
    int lane = tid & 31;
    int warp = tid >> 5;
    int wm = warp >> 2;              // 0..1  (m: rows wm*64..+64)
    int wn = warp & 3;               // 0..3  (n: cols wn*64..+64 within 256-tile)

    int bt = blockIdx.x;
    int b  = bt >> 8;
    const float* e_row = g_e + (size_t)bt * 640;
    const float* p_blk = g_p + (size_t)b * 128 * 640;
    float* out_blk = out + (size_t)bt * 128 * 1025;

    // ---- build h = bf16(relu(e + p)) into smem, pitch 648 ----
#pragma unroll 4
    for (int it = 0; it < 80; it++) {
        int idx = (it * 256 + tid) * 4;
        int u = idx / 640, j = idx - u * 640;
        float4 pv = *(const float4*)(p_blk + (size_t)u * 640 + j);
        float4 ev = *(const float4*)(e_row + j);
        __nv_bfloat16* hp = hs + u * HP + j;
        *(__nv_bfloat162*)(hp)     = __floats2bfloat162_rn(fmaxf(ev.x + pv.x, 0.f),
                                                           fmaxf(ev.y + pv.y, 0.f));
        *(__nv_bfloat162*)(hp + 2) = __floats2bfloat162_rn(fmaxf(ev.z + pv.z, 0.f),
                                                           fmaxf(ev.w + pv.w, 0.f));
    }
    __syncthreads();

    // preload W chunk 0 (overlaps with c=1024 column below)
    issue_chunk(wsm, 0, tid);
    asm volatile("cp.async.commit_group;\n" ::: "memory");

    // ---- column c = 1024 (scalar dot, initializes running stats) ----
    {
        int u = tid >> 1, half = tid & 1;
        const uint4* hv4 = (const uint4*)(hs + u * HP + half * 320);
        const uint4* wv4 = (const uint4*)(g_w + (size_t)1024 * 640 + half * 320);
        float acc = 0.f;
#pragma unroll 4
        for (int it = 0; it < 40; it++) {
            uint4 hv = hv4[it];
            uint4 wv = wv4[it];
            const uint32_t* hu = (const uint32_t*)&hv;
            const uint32_t* wu = (const uint32_t*)&wv;
#pragma unroll
            for (int q = 0; q < 4; q++) {
                float2 hf = __bfloat1622float2(*(const __nv_bfloat162*)&hu[q]);
                float2 wf = __bfloat1622float2(*(const __nv_bfloat162*)&wu[q]);
                acc += hf.x * wf.x + hf.y * wf.y;
            }
        }
        acc += __shfl_xor_sync(0xffffffffu, acc, 1);
        if (half == 0) {
            float logit = acc + bout[1024];
            out_blk[(size_t)u * 1025 + 1024] = logit;
            runM[u] = logit;
            runS[u] = 1.0f;
        }
    }

    // ---- 4 n-tiles of 256 columns ----
    for (int nt = 0; nt < 4; nt++) {
        float acc[4][8][4];
#pragma unroll
        for (int mi = 0; mi < 4; mi++)
#pragma unroll
            for (int nj = 0; nj < 8; nj++)
#pragma unroll
                for (int q = 0; q < 4; q++) acc[mi][nj][q] = 0.f;

        for (int kc = 0; kc < 20; kc++) {
            int g = nt * 20 + kc;
            if (g + 1 < 80) issue_chunk(wsm, g + 1, tid);
            asm volatile("cp.async.commit_group;\n" ::: "memory");
            if (g + 1 < 80) { asm volatile("cp.async.wait_group 1;\n" ::: "memory"); }
            else            { asm volatile("cp.async.wait_group 0;\n" ::: "memory"); }
            __syncthreads();

            uint32_t wb = wsm + (uint32_t)(g & 1) * WCHUNK;
#pragma unroll
            for (int ks2 = 0; ks2 < 2; ks2++) {
                int kglob = kc * 32 + ks2 * 16;
                uint32_t a[4][4];
                uint32_t abase = hsm +
                    (uint32_t)((wm * 64 + (lane & 15)) * HP + kglob + (lane >> 4) * 8) * 2;
#pragma unroll
                for (int mi = 0; mi < 4; mi++) ldsm4(a[mi], abase + mi * 16 * (HP * 2));

                uint32_t bf[4][4];
                uint32_t bbase = wb +
                    (uint32_t)(wn * 64 + (lane & 7) + ((lane >> 4) << 3)) * 80 +
                    ks2 * 32 + ((lane >> 3) & 1) * 16;
#pragma unroll
                for (int q = 0; q < 4; q++) ldsm4(bf[q], bbase + q * 16 * 80);

#pragma unroll
                for (int mi = 0; mi < 4; mi++)
#pragma unroll
                    for (int nj = 0; nj < 8; nj++)
                        mma16816(acc[mi][nj], a[mi], &bf[nj >> 1][(nj & 1) * 2]);
            }
            __syncthreads();
        }
        // (chunk for next tile's kc=0 is in flight into buf0; stage = buf1, free)

        // ---- epilogue: bias, per-row stats, staged coalesced stores ----
#pragma unroll
        for (int mi = 0; mi < 4; mi++) {
#pragma unroll
            for (int nj = 0; nj < 8; nj++) {
                int c = nt * 256 + wn * 64 + nj * 8 + (lane & 3) * 2;
                float2 bb = *(const float2*)(bout + c);
                acc[mi][nj][0] += bb.x; acc[mi][nj][1] += bb.y;
                acc[mi][nj][2] += bb.x; acc[mi][nj][3] += bb.y;
            }
#pragma unroll
            for (int rh = 0; rh < 2; rh++) {
                float m = -1e30f;
#pragma unroll
                for (int nj = 0; nj < 8; nj++) {
                    m = fmaxf(m, acc[mi][nj][rh * 2]);
                    m = fmaxf(m, acc[mi][nj][rh * 2 + 1]);
                }
                m = fmaxf(m, __shfl_xor_sync(0xffffffffu, m, 1));
                m = fmaxf(m, __shfl_xor_sync(0xffffffffu, m, 2));
                float s = 0.f;
#pragma unroll
                for (int nj = 0; nj < 8; nj++) {
                    s += __expf(acc[mi][nj][rh * 2] - m);
                    s += __expf(acc[mi][nj][rh * 2 + 1] - m);
                }
                s += __shfl_xor_sync(0xffffffffu, s, 1);
                s += __shfl_xor_sync(0xffffffffu, s, 2);
                if ((lane & 3) == 0) {
                    int r = wm * 64 + mi * 16 + (lane >> 2) + rh * 8;
                    wmax[wn * 128 + r] = m;
                    wsum[wn * 128 + r] = s;
                }
            }
        }

        // 8 passes of 32 columns through the rotated stage buffer
        for (int s = 0; s < 8; s++) {
            if (wn == (s >> 1)) {
                int sub = s & 1;
#pragma unroll
                for (int mi = 0; mi < 4; mi++)
#pragma unroll
                    for (int j = 0; j < 4; j++) {
                        int nj = sub * 4 + j;
                        int colL = j * 8 + (lane & 3) * 2;
#pragma unroll
                        for (int rh = 0; rh < 2; rh++) {
                            int r = wm * 64 + mi * 16 + (lane >> 2) + rh * 8;
                            int cc = (colL + ((r & 7) << 2)) & 31;
                            stage[r * 32 + cc]     = acc[mi][nj][rh * 2];
                            stage[r * 32 + cc + 1] = acc[mi][nj][rh * 2 + 1];
                        }
                    }
            }
            __syncthreads();
            float* ob = out_blk + nt * 256 + s * 32;
#pragma unroll
            for (int it = 0; it < 4; it++) {
                int idx = it * 256 + tid;
                int row = idx >> 3, v = idx & 7;
                int cc = ((v * 4) + ((row & 7) << 2)) & 31;
                float4 val = *(float4*)&stage[row * 32 + cc];
                // Row pitch 1025 floats: 16B stores misalign on 3/4 rows.
                // Scalar stores, still fully coalesced across the warp.
                float* op = ob + (size_t)row * 1025 + v * 4;
                op[0] = val.x; op[1] = val.y; op[2] = val.z; op[3] = val.w;
            }
            __syncthreads();
        }

        // merge per-row stats into running (max, sumexp)
        if (tid < 128) {
            float m = wmax[tid], s = wsum[tid];
#pragma unroll
            for (int q = 1; q < 4; q++) {
                float m2 = wmax[q * 128 + tid], s2 = wsum[q * 128 + tid];
                float nm = fmaxf(m, m2);
                s = s * __expf(m - nm) + s2 * __expf(m2 - nm);
                m = nm;
            }
            float rm = runM[tid], rs = runS[tid];
            float nm = fmaxf(rm, m);
            runS[tid] = rs * __expf(rm - nm) + s * __expf(m - nm);
            runM[tid] = nm;
        }
        __syncthreads();
    }

    // ---- finalize: lse, then normalize logits in place ----
    if (tid < 128) runM[tid] += logf(runS[tid]);
    __syncthreads();

    for (int i4 = tid; i4 < 32800; i4 += 256) {   // 128*1025/4
        float4* ptr = (float4*)out_blk + i4;
        float4 q = *ptr;
        int base = i4 * 4;
        q.x -= runM[base / 1025];
        q.y -= runM[(base + 1) / 1025];
        q.z -= runM[(base + 2) / 1025];
        q.w -= runM[(base + 3) / 1025];
        *ptr = q;
    }
}

// ---------------------------------------------------------------------------
extern "C" void kernel_launch(void* const* d_in, const int* in_sizes, int n_in,
                              void* d_out, int out_size) {
    const float* enc    = (const float*)d_in[0];
    const float* dec    = (const float*)d_in[1];
    const float* W_enc  = (const float*)d_in[2];
    const float* b_enc  = (const float*)d_in[3];
    const float* W_pred = (const float*)d_in[4];
    const float* b_pred = (const float*)d_in[5];
    const float* W_out  = (const float*)d_in[6];
    const float* b_out  = (const float*)d_in[7];
    float* out = (float*)d_out;

    convw_kernel<<<641, 256>>>(W_out);
    proj_kernel<<<dim3(16, 5), 256>>>(enc, W_enc, b_enc, E_, T_, 0);   // e
    proj_kernel<<<dim3(8, 5), 256>>>(dec, W_pred, b_pred, P_, U_, 1);  // p

    cudaFuncSetAttribute(joint_kernel,
                         cudaFuncAttributeMaxDynamicSharedMemorySize, SMEM_TOTAL);
    joint_kernel<<<2048, 256, SMEM_TOTAL>>>(b_out, out);
}

// round 9
// speedup vs baseline: 3.2217x; 3.2217x over previous
#include <cuda_runtime.h>
#include <cuda_bf16.h>
#include <cstdint>

// Shapes: enc [8,512,256], dec [8,640,128], W_enc [640,512], b_enc[640],
// W_pred [640,640], b_pred [640], W_out [1025,640], b_out[1025]
// out [8,256,128,1025] fp32
#define E_ 512
#define P_ 640
#define T_ 256
#define U_ 128

// Static scratch (no allocation)
__device__ __align__(16)  float         g_e[2048 * 640];   // [B*T, J]
__device__ __align__(16)  float         g_p[1024 * 640];   // [B*U, J]
__device__ __align__(256) __nv_bfloat16 g_w[1025 * 640];   // W_out bf16

// ---------------------------------------------------------------------------
// Kernel 0: W_out -> bf16
// ---------------------------------------------------------------------------
__global__ void convw_kernel(const float* __restrict__ w) {
    int i = blockIdx.x * 256 + threadIdx.x;
    if (i < (1025 * 640) / 4) {
        float4 v = *(const float4*)(w + (size_t)i * 4);
        *(__nv_bfloat162*)(g_w + (size_t)i * 4)     = __floats2bfloat162_rn(v.x, v.y);
        *(__nv_bfloat162*)(g_w + (size_t)i * 4 + 2) = __floats2bfloat162_rn(v.z, v.w);
    }
}

// ---------------------------------------------------------------------------
// Kernel 1: projection GEMM (fp32, exact) — proven
// ---------------------------------------------------------------------------
__global__ void __launch_bounds__(256) proj_kernel(
    const float* __restrict__ src, const float* __restrict__ W,
    const float* __restrict__ bias, int K, int X, int which)
{
    __shared__ float As[16][132];
    __shared__ float Bs[16][132];
    float* outp = which ? g_p : g_e;

    int m0 = blockIdx.x * 128;
    int j0 = blockIdx.y * 128;
    int b  = m0 / X;
    int x0 = m0 % X;
    int tid = threadIdx.x;
    int tm = tid & 15, tn = tid >> 4;

    float acc[8][8];
#pragma unroll
    for (int i = 0; i < 8; i++)
#pragma unroll
        for (int j = 0; j < 8; j++) acc[i][j] = 0.f;

    for (int k0 = 0; k0 < K; k0 += 16) {
        {
            int kk = tid >> 5;
            int ml = (tid & 31) * 4;
            const float* s = src + ((size_t)b * K + k0 + kk) * X + x0 + ml;
            float4 v0 = *(const float4*)s;
            float4 v1 = *(const float4*)(s + (size_t)8 * X);
            *(float4*)&As[kk][ml]     = v0;
            *(float4*)&As[kk + 8][ml] = v1;
        }
        {
            int j  = tid >> 2;
            int k4 = (tid & 3) * 4;
#pragma unroll
            for (int pass = 0; pass < 2; pass++) {
                int jj = j + pass * 64;
                float4 v = *(const float4*)(W + (size_t)(j0 + jj) * K + k0 + k4);
                Bs[k4 + 0][jj] = v.x; Bs[k4 + 1][jj] = v.y;
                Bs[k4 + 2][jj] = v.z; Bs[k4 + 3][jj] = v.w;
            }
        }
        __syncthreads();
#pragma unroll
        for (int kk = 0; kk < 16; kk++) {
            float a[8], bb[8];
            *(float4*)(a)      = *(float4*)&As[kk][tm * 8];
            *(float4*)(a + 4)  = *(float4*)&As[kk][tm * 8 + 4];
            *(float4*)(bb)     = *(float4*)&Bs[kk][tn * 8];
            *(float4*)(bb + 4) = *(float4*)&Bs[kk][tn * 8 + 4];
#pragma unroll
            for (int i = 0; i < 8; i++)
#pragma unroll
                for (int j = 0; j < 8; j++) acc[i][j] += a[i] * bb[j];
        }
        __syncthreads();
    }
#pragma unroll
    for (int i = 0; i < 8; i++) {
        int m = m0 + tm * 8 + i;
        float* orow = outp + (size_t)m * 640 + j0 + tn * 8;
#pragma unroll
        for (int j = 0; j < 8; j++) orow[j] = acc[i][j] + bias[j0 + tn * 8 + j];
    }
}

// ---------------------------------------------------------------------------
// PTX helpers (mma.sync path — tcgen05 unavailable in this toolchain)
// ---------------------------------------------------------------------------
__device__ __forceinline__ uint32_t smem_u32(const void* p) {
    return (uint32_t)__cvta_generic_to_shared(p);
}
__device__ __forceinline__ void ldsm4(uint32_t* r, uint32_t addr) {
    asm volatile("ldmatrix.sync.aligned.m8n8.x4.shared.b16 {%0,%1,%2,%3}, [%4];"
                 : "=r"(r[0]), "=r"(r[1]), "=r"(r[2]), "=r"(r[3]) : "r"(addr));
}
__device__ __forceinline__ void mma16816(float* c, const uint32_t* a, const uint32_t* b) {
    asm volatile(
        "mma.sync.aligned.m16n8k16.row.col.f32.bf16.bf16.f32 "
        "{%0,%1,%2,%3}, {%4,%5,%6,%7}, {%8,%9}, {%0,%1,%2,%3};"
        : "+f"(c[0]), "+f"(c[1]), "+f"(c[2]), "+f"(c[3])
        : "r"(a[0]), "r"(a[1]), "r"(a[2]), "r"(a[3]), "r"(b[0]), "r"(b[1]));
}
__device__ __forceinline__ void cp_async16(uint32_t dst, const void* src) {
    asm volatile("cp.async.cg.shared.global [%0], [%1], 16;\n" :: "r"(dst), "l"(src));
}

// ---------------------------------------------------------------------------
// Kernel 2: fused joint + HMMA GEMM + log_softmax
// One CTA per (b,t), 512 threads (16 warps, grid 4m x 4n), warp tile 32x64,
// CTA tile 128x256 over c; 4 n-tiles. h resident in smem (pitch 648 bf16).
// W streamed in [256 n][32 k] chunks (pitch 80B, cp.async double-buffered).
// Output staged through rotated smem buffer (aliased into W buf1); scalar
// coalesced gmem stores (row pitch 1025 floats).
// acc[2][8][4]=64 regs -> fits 128-reg cap at 512 threads, no spills.
// ---------------------------------------------------------------------------
#define HP 648                     // h pitch in bf16 (1296B rows)
#define WCHUNK 20480               // 256 rows * 80B
#define SM_A      0                // 128 * 1296 = 165888
#define SM_B      165888           // 2 * 20480 = 40960 (buf1 doubles as stage)
#define SM_STAGE  (SM_B + WCHUNK)  // 128*32 fp32 = 16384 (aliases buf1)
#define SM_WMAX   206848           // 4*128 fp32
#define SM_WSUM   208896           // 4*128 fp32
#define SM_RUNM   210944           // 128 fp32
#define SM_RUNS   211456           // 128 fp32
#define SMEM_TOTAL 211968

__device__ __forceinline__ void issue_chunk(uint32_t wsm, int g, int tid) {
    int nt = g / 20, kc = g - nt * 20;
    const char* src = (const char*)g_w + ((size_t)(nt * 256) * 640 + (size_t)kc * 32) * 2;
    uint32_t dst = wsm + (uint32_t)(g & 1) * WCHUNK;
#pragma unroll
    for (int it = 0; it < 2; it++) {
        int idx = it * 512 + tid;
        int row = idx >> 2, v = idx & 3;
        cp_async16(dst + row * 80 + v * 16, src + (size_t)row * 1280 + v * 16);
    }
}

__global__ void __launch_bounds__(512, 1) joint_kernel(
    const float* __restrict__ bout, float* __restrict__ out)
{
    extern __shared__ char sm[];
    __nv_bfloat16* hs = (__nv_bfloat16*)sm;
    float* stage = (float*)(sm + SM_STAGE);
    float* wmax  = (float*)(sm + SM_WMAX);
    float* wsum  = (float*)(sm + SM_WSUM);
    float* runM  = (float*)(sm + SM_RUNM);
    float* runS  = (float*)(sm + SM_RUNS);
    const uint32_t hsm = smem_u32(sm);
    const uint32_t wsm = hsm + SM_B;

    int tid  = threadIdx.x;
    int lane = tid & 31;
    int warp = tid >> 5;
    int wm = warp >> 2;              // 0..3  (m: rows wm*32..+32)
    int wn = warp & 3;               // 0..3  (n: cols wn*64..+64 within 256-tile)

    int bt = blockIdx.x;
    int b  = bt >> 8;
    const float* e_row = g_e + (size_t)bt * 640;
    const float* p_blk = g_p + (size_t)b * 128 * 640;
    float* out_blk = out + (size_t)bt * 128 * 1025;

    // ---- build h = bf16(relu(e + p)) into smem, pitch 648 ----
#pragma unroll 4
    for (int it = 0; it < 40; it++) {
        int idx = (it * 512 + tid) * 4;
        int u = idx / 640, j = idx - u * 640;
        float4 pv = *(const float4*)(p_blk + (size_t)u * 640 + j);
        float4 ev = *(const float4*)(e_row + j);
        __nv_bfloat16* hp = hs + u * HP + j;
        *(__nv_bfloat162*)(hp)     = __floats2bfloat162_rn(fmaxf(ev.x + pv.x, 0.f),
                                                           fmaxf(ev.y + pv.y, 0.f));
        *(__nv_bfloat162*)(hp + 2) = __floats2bfloat162_rn(fmaxf(ev.z + pv.z, 0.f),
                                                           fmaxf(ev.w + pv.w, 0.f));
    }
    __syncthreads();

    // preload W chunk 0 (overlaps with c=1024 column below)
    issue_chunk(wsm, 0, tid);
    asm volatile("cp.async.commit_group;\n" ::: "memory");

    // ---- column c = 1024 (scalar dot, initializes running stats) ----
    {
        int u = tid >> 2, qd = tid & 3;          // 128 u-rows x 4 quarters
        const uint4* hv4 = (const uint4*)(hs + u * HP + qd * 160);
        const uint4* wv4 = (const uint4*)(g_w + (size_t)1024 * 640 + qd * 160);
        float acc = 0.f;
#pragma unroll 4
        for (int it = 0; it < 20; it++) {
            uint4 hv = hv4[it];
            uint4 wv = wv4[it];
            const uint32_t* hu = (const uint32_t*)&hv;
            const uint32_t* wu = (const uint32_t*)&wv;
#pragma unroll
            for (int q = 0; q < 4; q++) {
                float2 hf = __bfloat1622float2(*(const __nv_bfloat162*)&hu[q]);
                float2 wf = __bfloat1622float2(*(const __nv_bfloat162*)&wu[q]);
                acc += hf.x * wf.x + hf.y * wf.y;
            }
        }
        acc += __shfl_xor_sync(0xffffffffu, acc, 1);
        acc += __shfl_xor_sync(0xffffffffu, acc, 2);
        if (qd == 0) {
            float logit = acc + bout[1024];
            out_blk[(size_t)u * 1025 + 1024] = logit;
            runM[u] = logit;
            runS[u] = 1.0f;
        }
    }

    // ---- 4 n-tiles of 256 columns ----
    for (int nt = 0; nt < 4; nt++) {
        float acc[2][8][4];
#pragma unroll
        for (int mi = 0; mi < 2; mi++)
#pragma unroll
            for (int nj = 0; nj < 8; nj++)
#pragma unroll
                for (int q = 0; q < 4; q++) acc[mi][nj][q] = 0.f;

        for (int kc = 0; kc < 20; kc++) {
            int g = nt * 20 + kc;
            if (g + 1 < 80) issue_chunk(wsm, g + 1, tid);
            asm volatile("cp.async.commit_group;\n" ::: "memory");
            if (g + 1 < 80) { asm volatile("cp.async.wait_group 1;\n" ::: "memory"); }
            else            { asm volatile("cp.async.wait_group 0;\n" ::: "memory"); }
            __syncthreads();

            uint32_t wb = wsm + (uint32_t)(g & 1) * WCHUNK;
#pragma unroll
            for (int ks2 = 0; ks2 < 2; ks2++) {
                int kglob = kc * 32 + ks2 * 16;
                uint32_t a[2][4];
                uint32_t abase = hsm +
                    (uint32_t)((wm * 32 + (lane & 15)) * HP + kglob + (lane >> 4) * 8) * 2;
#pragma unroll
                for (int mi = 0; mi < 2; mi++) ldsm4(a[mi], abase + mi * 16 * (HP * 2));

                uint32_t bf[4][4];
                uint32_t bbase = wb +
                    (uint32_t)(wn * 64 + (lane & 7) + ((lane >> 4) << 3)) * 80 +
                    ks2 * 32 + ((lane >> 3) & 1) * 16;
#pragma unroll
                for (int q = 0; q < 4; q++) ldsm4(bf[q], bbase + q * 16 * 80);

#pragma unroll
                for (int mi = 0; mi < 2; mi++)
#pragma unroll
                    for (int nj = 0; nj < 8; nj++)
                        mma16816(acc[mi][nj], a[mi], &bf[nj >> 1][(nj & 1) * 2]);
            }
            __syncthreads();
        }
        // (chunk for next tile's kc=0 in flight into buf0; stage = buf1, free)

        // ---- epilogue: bias, per-row stats ----
#pragma unroll
        for (int mi = 0; mi < 2; mi++) {
#pragma unroll
            for (int nj = 0; nj < 8; nj++) {
                int c = nt * 256 + wn * 64 + nj * 8 + (lane & 3) * 2;
                float2 bb = *(const float2*)(bout + c);
                acc[mi][nj][0] += bb.x; acc[mi][nj][1] += bb.y;
                acc[mi][nj][2] += bb.x; acc[mi][nj][3] += bb.y;
            }
#pragma unroll
            for (int rh = 0; rh < 2; rh++) {
                float m = -1e30f;
#pragma unroll
                for (int nj = 0; nj < 8; nj++) {
                    m = fmaxf(m, acc[mi][nj][rh * 2]);
                    m = fmaxf(m, acc[mi][nj][rh * 2 + 1]);
                }
                m = fmaxf(m, __shfl_xor_sync(0xffffffffu, m, 1));
                m = fmaxf(m, __shfl_xor_sync(0xffffffffu, m, 2));
                float s = 0.f;
#pragma unroll
                for (int nj = 0; nj < 8; nj++) {
                    s += __expf(acc[mi][nj][rh * 2] - m);
                    s += __expf(acc[mi][nj][rh * 2 + 1] - m);
                }
                s += __shfl_xor_sync(0xffffffffu, s, 1);
                s += __shfl_xor_sync(0xffffffffu, s, 2);
                if ((lane & 3) == 0) {
                    int r = wm * 32 + mi * 16 + (lane >> 2) + rh * 8;
                    wmax[wn * 128 + r] = m;
                    wsum[wn * 128 + r] = s;
                }
            }
        }

        // 8 passes of 32 columns through the rotated stage buffer
        for (int s = 0; s < 8; s++) {
            if (wn == (s >> 1)) {
                int sub = s & 1;
#pragma unroll
                for (int mi = 0; mi < 2; mi++)
#pragma unroll
                    for (int j = 0; j < 4; j++) {
                        int nj = sub * 4 + j;
                        int colL = j * 8 + (lane & 3) * 2;
#pragma unroll
                        for (int rh = 0; rh < 2; rh++) {
                            int r = wm * 32 + mi * 16 + (lane >> 2) + rh * 8;
                            int cc = (colL + ((r & 7) << 2)) & 31;
                            stage[r * 32 + cc]     = acc[mi][nj][rh * 2];
                            stage[r * 32 + cc + 1] = acc[mi][nj][rh * 2 + 1];
                        }
                    }
            }
            __syncthreads();
            float* ob = out_blk + nt * 256 + s * 32;
#pragma unroll
            for (int it = 0; it < 2; it++) {
                int idx = it * 512 + tid;
                int row = idx >> 3, v = idx & 7;
                int cc = ((v * 4) + ((row & 7) << 2)) & 31;
                float4 val = *(float4*)&stage[row * 32 + cc];
                // Row pitch 1025 floats: scalar stores, coalesced across warp.
                float* op = ob + (size_t)row * 1025 + v * 4;
                op[0] = val.x; op[1] = val.y; op[2] = val.z; op[3] = val.w;
            }
            __syncthreads();
        }

        // merge per-row stats into running (max, sumexp)
        if (tid < 128) {
            float m = wmax[tid], s = wsum[tid];
#pragma unroll
            for (int q = 1; q < 4; q++) {
                float m2 = wmax[q * 128 + tid], s2 = wsum[q * 128 + tid];
                float nm = fmaxf(m, m2);
                s = s * __expf(m - nm) + s2 * __expf(m2 - nm);
                m = nm;
            }
            float rm = runM[tid], rs = runS[tid];
            float nm = fmaxf(rm, m);
            runS[tid] = rs * __expf(rm - nm) + s * __expf(m - nm);
            runM[tid] = nm;
        }
        __syncthreads();
    }

    // ---- finalize: lse, then normalize logits in place ----
    if (tid < 128) runM[tid] += logf(runS[tid]);
    __syncthreads();

    for (int i4 = tid; i4 < 32800; i4 += 512) {   // 128*1025/4, block base 16B-aligned
        float4* ptr = (float4*)out_blk + i4;
        float4 q = *ptr;
        int base = i4 * 4;
        q.x -= runM[base / 1025];
        q.y -= runM[(base + 1) / 1025];
        q.z -= runM[(base + 2) / 1025];
        q.w -= runM[(base + 3) / 1025];
        *ptr = q;
    }
}

// ---------------------------------------------------------------------------
extern "C" void kernel_launch(void* const* d_in, const int* in_sizes, int n_in,
                              void* d_out, int out_size) {
    const float* enc    = (const float*)d_in[0];
    const float* dec    = (const float*)d_in[1];
    const float* W_enc  = (const float*)d_in[2];
    const float* b_enc  = (const float*)d_in[3];
    const float* W_pred = (const float*)d_in[4];
    const float* b_pred = (const float*)d_in[5];
    const float* W_out  = (const float*)d_in[6];
    const float* b_out  = (const float*)d_in[7];
    float* out = (float*)d_out;

    convw_kernel<<<641, 256>>>(W_out);
    proj_kernel<<<dim3(16, 5), 256>>>(enc, W_enc, b_enc, E_, T_, 0);   // e
    proj_kernel<<<dim3(8, 5), 256>>>(dec, W_pred, b_pred, P_, U_, 1);  // p

    cudaFuncSetAttribute(joint_kernel,
                         cudaFuncAttributeMaxDynamicSharedMemorySize, SMEM_TOTAL);
    joint_kernel<<<2048, 512, SMEM_TOTAL>>>(b_out, out);
}

// round 11
// speedup vs baseline: 3.9095x; 1.2135x over previous
#include <cuda_runtime.h>
#include <cuda_bf16.h>
#include <cstdint>

// Shapes: enc [8,512,256], dec [8,640,128], W_enc [640,512], b_enc[640],
// W_pred [640,640], b_pred [640], W_out [1025,640], b_out[1025]
// out [8,256,128,1025] fp32
#define E_ 512
#define P_ 640
#define T_ 256
#define U_ 128

// Static scratch (no allocation)
__device__ __align__(16)  float         g_e[2048 * 640];   // [B*T, J]
__device__ __align__(16)  float         g_p[1024 * 640];   // [B*U, J]
__device__ __align__(256) __nv_bfloat16 g_w[1025 * 640];   // W_out bf16

// ---------------------------------------------------------------------------
// Kernel 0: W_out -> bf16
// ---------------------------------------------------------------------------
__global__ void convw_kernel(const float* __restrict__ w) {
    int i = blockIdx.x * 256 + threadIdx.x;
    if (i < (1025 * 640) / 4) {
        float4 v = *(const float4*)(w + (size_t)i * 4);
        *(__nv_bfloat162*)(g_w + (size_t)i * 4)     = __floats2bfloat162_rn(v.x, v.y);
        *(__nv_bfloat162*)(g_w + (size_t)i * 4 + 2) = __floats2bfloat162_rn(v.z, v.w);
    }
}

// ---------------------------------------------------------------------------
// Kernel 1: projection GEMM (fp32, exact) — proven
// ---------------------------------------------------------------------------
__global__ void __launch_bounds__(256) proj_kernel(
    const float* __restrict__ src, const float* __restrict__ W,
    const float* __restrict__ bias, int K, int X, int which)
{
    __shared__ float As[16][132];
    __shared__ float Bs[16][132];
    float* outp = which ? g_p : g_e;

    int m0 = blockIdx.x * 128;
    int j0 = blockIdx.y * 128;
    int b  = m0 / X;
    int x0 = m0 % X;
    int tid = threadIdx.x;
    int tm = tid & 15, tn = tid >> 4;

    float acc[8][8];
#pragma unroll
    for (int i = 0; i < 8; i++)
#pragma unroll
        for (int j = 0; j < 8; j++) acc[i][j] = 0.f;

    for (int k0 = 0; k0 < K; k0 += 16) {
        {
            int kk = tid >> 5;
            int ml = (tid & 31) * 4;
            const float* s = src + ((size_t)b * K + k0 + kk) * X + x0 + ml;
            float4 v0 = *(const float4*)s;
            float4 v1 = *(const float4*)(s + (size_t)8 * X);
            *(float4*)&As[kk][ml]     = v0;
            *(float4*)&As[kk + 8][ml] = v1;
        }
        {
            int j  = tid >> 2;
            int k4 = (tid & 3) * 4;
#pragma unroll
            for (int pass = 0; pass < 2; pass++) {
                int jj = j + pass * 64;
                float4 v = *(const float4*)(W + (size_t)(j0 + jj) * K + k0 + k4);
                Bs[k4 + 0][jj] = v.x; Bs[k4 + 1][jj] = v.y;
                Bs[k4 + 2][jj] = v.z; Bs[k4 + 3][jj] = v.w;
            }
        }
        __syncthreads();
#pragma unroll
        for (int kk = 0; kk < 16; kk++) {
            float a[8], bb[8];
            *(float4*)(a)      = *(float4*)&As[kk][tm * 8];
            *(float4*)(a + 4)  = *(float4*)&As[kk][tm * 8 + 4];
            *(float4*)(bb)     = *(float4*)&Bs[kk][tn * 8];
            *(float4*)(bb + 4) = *(float4*)&Bs[kk][tn * 8 + 4];
#pragma unroll
            for (int i = 0; i < 8; i++)
#pragma unroll
                for (int j = 0; j < 8; j++) acc[i][j] += a[i] * bb[j];
        }
        __syncthreads();
    }
#pragma unroll
    for (int i = 0; i < 8; i++) {
        int m = m0 + tm * 8 + i;
        float* orow = outp + (size_t)m * 640 + j0 + tn * 8;
#pragma unroll
        for (int j = 0; j < 8; j++) orow[j] = acc[i][j] + bias[j0 + tn * 8 + j];
    }
}

// ---------------------------------------------------------------------------
// PTX helpers
// ---------------------------------------------------------------------------
__device__ __forceinline__ uint32_t smem_u32(const void* p) {
    return (uint32_t)__cvta_generic_to_shared(p);
}
__device__ __forceinline__ void ldsm4(uint32_t* r, uint32_t addr) {
    asm volatile("ldmatrix.sync.aligned.m8n8.x4.shared.b16 {%0,%1,%2,%3}, [%4];"
                 : "=r"(r[0]), "=r"(r[1]), "=r"(r[2]), "=r"(r[3]) : "r"(addr));
}
__device__ __forceinline__ void mma16816(float* c, const uint32_t* a, const uint32_t* b) {
    asm volatile(
        "mma.sync.aligned.m16n8k16.row.col.f32.bf16.bf16.f32 "
        "{%0,%1,%2,%3}, {%4,%5,%6,%7}, {%8,%9}, {%0,%1,%2,%3};"
        : "+f"(c[0]), "+f"(c[1]), "+f"(c[2]), "+f"(c[3])
        : "r"(a[0]), "r"(a[1]), "r"(a[2]), "r"(a[3]), "r"(b[0]), "r"(b[1]));
}
__device__ __forceinline__ void cp_async16(uint32_t dst, const void* src) {
    asm volatile("cp.async.cg.shared.global [%0], [%1], 16;\n" :: "r"(dst), "l"(src));
}
__device__ __forceinline__ void bar_sync(int id) {
    asm volatile("bar.sync %0, 256;" :: "r"(id) : "memory");
}

// ---------------------------------------------------------------------------
// Kernel 2: fused joint + HMMA GEMM + log_softmax, DUAL-PIPELINE CTA.
// One CTA per (b,t), 512 threads. Warps 0-7 = half 0 (cols 0..511),
// warps 8-15 = half 1 (cols 512..1023). Each half: independent named-barrier
// domain, own W double-buffer (8KB chunks, cp.async), own running softmax
// stats. Warp tile 32x64 (grid 4m x 2n per half), ONE barrier per kc.
// h shared in smem (pitch 648 bf16). Direct fragment stores for logits.
// c=1024 handled by a scalar dot before the split. Final: merge halves' stats,
// flat float4 normalize pass.
// ---------------------------------------------------------------------------
#define HP 648                     // h pitch in bf16 (1296B rows)
#define WCHUNK 10240               // 128 n-rows * 80B
#define SM_A      0                // 128 * 1296 = 165888
#define SM_B      165888           // 2 halves * 2 bufs * 10240 = 40960
#define SM_WMAX   206848           // [4][128] fp32 ((half*2+wn)*128)
#define SM_WSUM   208896           // [4][128] fp32
#define SM_RUNM   210944           // [2][128] fp32
#define SM_RUNS   211968           // [2][128] fp32
#define SMEM_TOTAL 212992

// chunk g (0..79) of a half: nt = g/20 (128-col tile), kc = g%20 (32-k slab)
__device__ __forceinline__ void issue_chunk(uint32_t wsm_h, int half, int g, int htid) {
    int nt = g / 20, kc = g - nt * 20;
    const char* src = (const char*)g_w +
        ((size_t)(half * 512 + nt * 128) * 640 + (size_t)kc * 32) * 2;
    uint32_t dst = wsm_h + (uint32_t)(g & 1) * WCHUNK;
#pragma unroll
    for (int it = 0; it < 2; it++) {
        int idx = it * 256 + htid;        // 512 x 16B = 8KB
        int row = idx >> 2, v = idx & 3;
        cp_async16(dst + row * 80 + v * 16, src + (size_t)row * 1280 + v * 16);
    }
}

__global__ void __launch_bounds__(512, 1) joint_kernel(
    const float* __restrict__ bout, float* __restrict__ out)
{
    extern __shared__ char sm[];
    __nv_bfloat16* hs = (__nv_bfloat16*)sm;
    float* wmax  = (float*)(sm + SM_WMAX);
    float* wsum  = (float*)(sm + SM_WSUM);
    float* runM  = (float*)(sm + SM_RUNM);   // [2][128]
    float* runS  = (float*)(sm + SM_RUNS);
    const uint32_t hsm = smem_u32(sm);

    int tid  = threadIdx.x;
    int lane = tid & 31;
    int warp = tid >> 5;
    int half = warp >> 3;            // 0 or 1
    int w8   = warp & 7;
    int wm   = w8 >> 1;              // 0..3 (rows wm*32..+32)
    int wn   = w8 & 1;               // 0..1 (cols wn*64..+64 within 128-tile)
    int htid = tid & 255;
    const uint32_t wsm_h = hsm + SM_B + (uint32_t)half * (2 * WCHUNK);

    int bt = blockIdx.x;
    int b  = bt >> 8;
    const float* e_row = g_e + (size_t)bt * 640;
    const float* p_blk = g_p + (size_t)b * 128 * 640;
    float* out_blk = out + (size_t)bt * 128 * 1025;

    // preload own half's chunk 0 immediately (overlaps h build)
    issue_chunk(wsm_h, half, 0, htid);
    asm volatile("cp.async.commit_group;\n" ::: "memory");

    // ---- build h = bf16(relu(e + p)) into smem, pitch 648 ----
#pragma unroll 4
    for (int it = 0; it < 40; it++) {
        int idx = (it * 512 + tid) * 4;
        int u = idx / 640, j = idx - u * 640;
        float4 pv = *(const float4*)(p_blk + (size_t)u * 640 + j);
        float4 ev = *(const float4*)(e_row + j);
        __nv_bfloat16* hp = hs + u * HP + j;
        *(__nv_bfloat162*)(hp)     = __floats2bfloat162_rn(fmaxf(ev.x + pv.x, 0.f),
                                                           fmaxf(ev.y + pv.y, 0.f));
        *(__nv_bfloat162*)(hp + 2) = __floats2bfloat162_rn(fmaxf(ev.z + pv.z, 0.f),
                                                           fmaxf(ev.w + pv.w, 0.f));
    }
    __syncthreads();

    // ---- column c = 1024 (scalar dot); init running stats (half0 = real,
    //      half1 = neutral) ----
    {
        int u = tid >> 2, qd = tid & 3;
        const uint4* hv4 = (const uint4*)(hs + u * HP + qd * 160);
        const uint4* wv4 = (const uint4*)(g_w + (size_t)1024 * 640 + qd * 160);
        float acc = 0.f;
#pragma unroll 4
        for (int it = 0; it < 20; it++) {
            uint4 hv = hv4[it];
            uint4 wv = wv4[it];
            const uint32_t* hu = (const uint32_t*)&hv;
            const uint32_t* wu = (const uint32_t*)&wv;
#pragma unroll
            for (int q = 0; q < 4; q++) {
                float2 hf = __bfloat1622float2(*(const __nv_bfloat162*)&hu[q]);
                float2 wf = __bfloat1622float2(*(const __nv_bfloat162*)&wu[q]);
                acc += hf.x * wf.x + hf.y * wf.y;
            }
        }
        acc += __shfl_xor_sync(0xffffffffu, acc, 1);
        acc += __shfl_xor_sync(0xffffffffu, acc, 2);
        if (qd == 0) {
            float logit = acc + bout[1024];
            out_blk[(size_t)u * 1025 + 1024] = logit;
            runM[u] = logit;  runS[u] = 1.0f;          // half 0 running
            runM[128 + u] = -1e30f;  runS[128 + u] = 0.f;  // half 1 running
        }
    }
    __syncthreads();

    // ================= per-half independent pipeline =================
    int barid = 1 + half;
    for (int nt = 0; nt < 4; nt++) {
        float acc[2][8][4];
#pragma unroll
        for (int mi = 0; mi < 2; mi++)
#pragma unroll
            for (int nj = 0; nj < 8; nj++)
#pragma unroll
                for (int q = 0; q < 4; q++) acc[mi][nj][q] = 0.f;

        for (int kc = 0; kc < 20; kc++) {
            int g = nt * 20 + kc;
            asm volatile("cp.async.wait_group 0;\n" ::: "memory");
            bar_sync(barid);
            if (g < 79) {
                issue_chunk(wsm_h, half, g + 1, htid);
                asm volatile("cp.async.commit_group;\n" ::: "memory");
            }

            uint32_t wb = wsm_h + (uint32_t)(g & 1) * WCHUNK;
#pragma unroll
            for (int ks2 = 0; ks2 < 2; ks2++) {
                int kglob = kc * 32 + ks2 * 16;
                uint32_t a[2][4];
                uint32_t abase = hsm +
                    (uint32_t)((wm * 32 + (lane & 15)) * HP + kglob + (lane >> 4) * 8) * 2;
#pragma unroll
                for (int mi = 0; mi < 2; mi++) ldsm4(a[mi], abase + mi * 16 * (HP * 2));

                uint32_t bf[4][4];
                uint32_t bbase = wb +
                    (uint32_t)(wn * 64 + (lane & 7) + ((lane >> 4) << 3)) * 80 +
                    ks2 * 32 + ((lane >> 3) & 1) * 16;
#pragma unroll
                for (int q = 0; q < 4; q++) ldsm4(bf[q], bbase + q * 16 * 80);

#pragma unroll
                for (int mi = 0; mi < 2; mi++)
#pragma unroll
                    for (int nj = 0; nj < 8; nj++)
                        mma16816(acc[mi][nj], a[mi], &bf[nj >> 1][(nj & 1) * 2]);
            }
            // single barrier per kc: next iteration's bar (after all LDSM
            // complete) protects buf reuse.
        }

        // ---- epilogue: bias, per-row (max,sum) stats ----
        int cbase = half * 512 + nt * 128 + wn * 64;
#pragma unroll
        for (int mi = 0; mi < 2; mi++) {
#pragma unroll
            for (int nj = 0; nj < 8; nj++) {
                int c = cbase + nj * 8 + (lane & 3) * 2;
                float2 bb = *(const float2*)(bout + c);
                acc[mi][nj][0] += bb.x; acc[mi][nj][1] += bb.y;
                acc[mi][nj][2] += bb.x; acc[mi][nj][3] += bb.y;
            }
#pragma unroll
            for (int rh = 0; rh < 2; rh++) {
                float m = -1e30f;
#pragma unroll
                for (int nj = 0; nj < 8; nj++) {
                    m = fmaxf(m, acc[mi][nj][rh * 2]);
                    m = fmaxf(m, acc[mi][nj][rh * 2 + 1]);
                }
                m = fmaxf(m, __shfl_xor_sync(0xffffffffu, m, 1));
                m = fmaxf(m, __shfl_xor_sync(0xffffffffu, m, 2));
                float s = 0.f;
#pragma unroll
                for (int nj = 0; nj < 8; nj++) {
                    s += __expf(acc[mi][nj][rh * 2] - m);
                    s += __expf(acc[mi][nj][rh * 2 + 1] - m);
                }
                s += __shfl_xor_sync(0xffffffffu, s, 1);
                s += __shfl_xor_sync(0xffffffffu, s, 2);
                if ((lane & 3) == 0) {
                    int r = wm * 32 + mi * 16 + (lane >> 2) + rh * 8;
                    wmax[(half * 2 + wn) * 128 + r] = m;
                    wsum[(half * 2 + wn) * 128 + r] = s;
                }
            }
        }
        bar_sync(barid);
        // merge the half's 2 n-warp-groups into its running stats
        if (htid < 128) {
            int u = htid;
            float m0 = wmax[(half * 2) * 128 + u],     s0 = wsum[(half * 2) * 128 + u];
            float m1 = wmax[(half * 2 + 1) * 128 + u], s1 = wsum[(half * 2 + 1) * 128 + u];
            float nm = fmaxf(m0, m1);
            float ss = s0 * __expf(m0 - nm) + s1 * __expf(m1 - nm);
            float rm = runM[half * 128 + u], rs = runS[half * 128 + u];
            float nm2 = fmaxf(rm, nm);
            runS[half * 128 + u] = rs * __expf(rm - nm2) + ss * __expf(nm - nm2);
            runM[half * 128 + u] = nm2;
        }
        // (next kc-barrier orders wmax reuse; no extra bar needed)

        // ---- direct logit stores from fragments (coalesced-ish, scalar) ----
#pragma unroll
        for (int mi = 0; mi < 2; mi++) {
            int r0 = wm * 32 + mi * 16 + (lane >> 2);
#pragma unroll
            for (int nj = 0; nj < 8; nj++) {
                int c = cbase + nj * 8 + (lane & 3) * 2;
                float* o0 = out_blk + (size_t)r0 * 1025 + c;
                o0[0] = acc[mi][nj][0]; o0[1] = acc[mi][nj][1];
                float* o1 = o0 + (size_t)8 * 1025;
                o1[0] = acc[mi][nj][2]; o1[1] = acc[mi][nj][3];
            }
        }
    }

    // ================= finalize =================
    __syncthreads();
    if (tid < 128) {
        float mA = runM[tid], sA = runS[tid];
        float mB = runM[128 + tid], sB = runS[128 + tid];
        float nm = fmaxf(mA, mB);
        float s  = sA * __expf(mA - nm) + sB * __expf(mB - nm);
        runM[tid] = nm + logf(s);     // lse per row
    }
    __syncthreads();

    for (int i4 = tid; i4 < 32800; i4 += 512) {   // 128*1025/4, block base aligned
        float4* ptr = (float4*)out_blk + i4;
        float4 q = *ptr;
        int base = i4 * 4;
        q.x -= runM[base / 1025];
        q.y -= runM[(base + 1) / 1025];
        q.z -= runM[(base + 2) / 1025];
        q.w -= runM[(base + 3) / 1025];
        *ptr = q;
    }
}

// ---------------------------------------------------------------------------
extern "C" void kernel_launch(void* const* d_in, const int* in_sizes, int n_in,
                              void* d_out, int out_size) {
    const float* enc    = (const float*)d_in[0];
    const float* dec    = (const float*)d_in[1];
    const float* W_enc  = (const float*)d_in[2];
    const float* b_enc  = (const float*)d_in[3];
    const float* W_pred = (const float*)d_in[4];
    const float* b_pred = (const float*)d_in[5];
    const float* W_out  = (const float*)d_in[6];
    const float* b_out  = (const float*)d_in[7];
    float* out = (float*)d_out;

    convw_kernel<<<641, 256>>>(W_out);
    proj_kernel<<<dim3(16, 5), 256>>>(enc, W_enc, b_enc, E_, T_, 0);   // e
    proj_kernel<<<dim3(8, 5), 256>>>(dec, W_pred, b_pred, P_, U_, 1);  // p

    cudaFuncSetAttribute(joint_kernel,
                         cudaFuncAttributeMaxDynamicSharedMemorySize, SMEM_TOTAL);
    joint_kernel<<<2048, 512, SMEM_TOTAL>>>(b_out, out);
}

// round 13
// speedup vs baseline: 4.2016x; 1.0747x over previous
#include <cuda_runtime.h>
#include <cuda_bf16.h>
#include <cstdint>

// Shapes: enc [8,512,256], dec [8,640,128], W_enc [640,512], b_enc[640],
// W_pred [640,640], b_pred [640], W_out [1025,640], b_out[1025]
// out [8,256,128,1025] fp32
#define E_ 512
#define P_ 640
#define T_ 256
#define U_ 128

// Static scratch (no allocation)
__device__ __align__(16)  float         g_e[2048 * 640];   // [B*T, J]
__device__ __align__(16)  float         g_p[1024 * 640];   // [B*U, J]
__device__ __align__(256) __nv_bfloat16 g_w[1025 * 640];   // W_out bf16

// ---------------------------------------------------------------------------
// Kernel 0: W_out -> bf16
// ---------------------------------------------------------------------------
__global__ void convw_kernel(const float* __restrict__ w) {
    int i = blockIdx.x * 256 + threadIdx.x;
    if (i < (1025 * 640) / 4) {
        float4 v = *(const float4*)(w + (size_t)i * 4);
        *(__nv_bfloat162*)(g_w + (size_t)i * 4)     = __floats2bfloat162_rn(v.x, v.y);
        *(__nv_bfloat162*)(g_w + (size_t)i * 4 + 2) = __floats2bfloat162_rn(v.z, v.w);
    }
}

// ---------------------------------------------------------------------------
// Kernel 1: projection GEMM (fp32, exact) — proven
// ---------------------------------------------------------------------------
__global__ void __launch_bounds__(256) proj_kernel(
    const float* __restrict__ src, const float* __restrict__ W,
    const float* __restrict__ bias, int K, int X, int which)
{
    __shared__ float As[16][132];
    __shared__ float Bs[16][132];
    float* outp = which ? g_p : g_e;

    int m0 = blockIdx.x * 128;
    int j0 = blockIdx.y * 128;
    int b  = m0 / X;
    int x0 = m0 % X;
    int tid = threadIdx.x;
    int tm = tid & 15, tn = tid >> 4;

    float acc[8][8];
#pragma unroll
    for (int i = 0; i < 8; i++)
#pragma unroll
        for (int j = 0; j < 8; j++) acc[i][j] = 0.f;

    for (int k0 = 0; k0 < K; k0 += 16) {
        {
            int kk = tid >> 5;
            int ml = (tid & 31) * 4;
            const float* s = src + ((size_t)b * K + k0 + kk) * X + x0 + ml;
            float4 v0 = *(const float4*)s;
            float4 v1 = *(const float4*)(s + (size_t)8 * X);
            *(float4*)&As[kk][ml]     = v0;
            *(float4*)&As[kk + 8][ml] = v1;
        }
        {
            int j  = tid >> 2;
            int k4 = (tid & 3) * 4;
#pragma unroll
            for (int pass = 0; pass < 2; pass++) {
                int jj = j + pass * 64;
                float4 v = *(const float4*)(W + (size_t)(j0 + jj) * K + k0 + k4);
                Bs[k4 + 0][jj] = v.x; Bs[k4 + 1][jj] = v.y;
                Bs[k4 + 2][jj] = v.z; Bs[k4 + 3][jj] = v.w;
            }
        }
        __syncthreads();
#pragma unroll
        for (int kk = 0; kk < 16; kk++) {
            float a[8], bb[8];
            *(float4*)(a)      = *(float4*)&As[kk][tm * 8];
            *(float4*)(a + 4)  = *(float4*)&As[kk][tm * 8 + 4];
            *(float4*)(bb)     = *(float4*)&Bs[kk][tn * 8];
            *(float4*)(bb + 4) = *(float4*)&Bs[kk][tn * 8 + 4];
#pragma unroll
            for (int i = 0; i < 8; i++)
#pragma unroll
                for (int j = 0; j < 8; j++) acc[i][j] += a[i] * bb[j];
        }
        __syncthreads();
    }
#pragma unroll
    for (int i = 0; i < 8; i++) {
        int m = m0 + tm * 8 + i;
        float* orow = outp + (size_t)m * 640 + j0 + tn * 8;
#pragma unroll
        for (int j = 0; j < 8; j++) orow[j] = acc[i][j] + bias[j0 + tn * 8 + j];
    }
}

// ---------------------------------------------------------------------------
// PTX helpers
// ---------------------------------------------------------------------------
__device__ __forceinline__ uint32_t smem_u32(const void* p) {
    return (uint32_t)__cvta_generic_to_shared(p);
}
__device__ __forceinline__ void ldsm4(uint32_t* r, uint32_t addr) {
    asm volatile("ldmatrix.sync.aligned.m8n8.x4.shared.b16 {%0,%1,%2,%3}, [%4];"
                 : "=r"(r[0]), "=r"(r[1]), "=r"(r[2]), "=r"(r[3]) : "r"(addr));
}
__device__ __forceinline__ void mma16816(float* c, const uint32_t* a, const uint32_t* b) {
    asm volatile(
        "mma.sync.aligned.m16n8k16.row.col.f32.bf16.bf16.f32 "
        "{%0,%1,%2,%3}, {%4,%5,%6,%7}, {%8,%9}, {%0,%1,%2,%3};"
        : "+f"(c[0]), "+f"(c[1]), "+f"(c[2]), "+f"(c[3])
        : "r"(a[0]), "r"(a[1]), "r"(a[2]), "r"(a[3]), "r"(b[0]), "r"(b[1]));
}
__device__ __forceinline__ void cp_async16(uint32_t dst, const void* src) {
    asm volatile("cp.async.cg.shared.global [%0], [%1], 16;\n" :: "r"(dst), "l"(src));
}
__device__ __forceinline__ void bar_sync128(int id) {
    asm volatile("bar.sync %0, 128;" :: "r"(id) : "memory");
}

// ---------------------------------------------------------------------------
// Kernel 2: fused joint + HMMA GEMM + log_softmax, QUAD-PIPELINE CTA.
// One CTA per (b,t), 512 threads = 4 independent pipelines of 4 warps.
// Quarter q owns cols q*256..+256 (4 n-subtiles of 64), own W double-buffer
// (64n x 32k chunks, 5KB, pitch 80B), own 128-thread named barrier, own
// running softmax stats. Warp tile 64x32 (2m x 2n per quarter).
// A-fragments (h) are software-pipelined ACROSS the chunk barrier (h is
// read-only smem) so LDS latency hides under the MMA burst.
// h shared in smem (pitch 648 bf16). Direct fragment logit stores.
// c=1024 via scalar dot. Final: merge 4 quarters' stats, flat normalize.
// ---------------------------------------------------------------------------
#define HP 648                     // h pitch in bf16 (1296B rows)
#define QCHUNK 5120                // 64 n-rows * 80B
#define SM_A      0                // 128 * 1296 = 165888
#define SM_B      165888           // 4 quarters * 2 bufs * 5120 = 40960
#define SM_WMAX   206848           // [8][128] fp32 ((q*2+wn)*128)
#define SM_WSUM   210944           // [8][128] fp32
#define SM_RUNM   215040           // [4][128] fp32
#define SM_RUNS   217088           // [4][128] fp32
#define SMEM_TOTAL 219136

// chunk g (0..79) of quarter q: nt = g/20 (64-col subtile), kc = g%20 (32-k)
__device__ __forceinline__ void issue_chunk(uint32_t wsm_q, int q, int g, int qtid) {
    int nt = g / 20, kc = g - nt * 20;
    const char* src = (const char*)g_w +
        ((size_t)(q * 256 + nt * 64) * 640 + (size_t)kc * 32) * 2;
    uint32_t dst = wsm_q + (uint32_t)(g & 1) * QCHUNK;
#pragma unroll
    for (int it = 0; it < 2; it++) {
        int idx = it * 128 + qtid;        // 256 x 16B = 4KB data
        int row = idx >> 2, v = idx & 3;
        cp_async16(dst + row * 80 + v * 16, src + (size_t)row * 1280 + v * 16);
    }
}

__global__ void __launch_bounds__(512, 1) joint_kernel(
    const float* __restrict__ bout, float* __restrict__ out)
{
    extern __shared__ char sm[];
    __nv_bfloat16* hs = (__nv_bfloat16*)sm;
    float* wmax  = (float*)(sm + SM_WMAX);
    float* wsum  = (float*)(sm + SM_WSUM);
    float* runM  = (float*)(sm + SM_RUNM);   // [4][128]
    float* runS  = (float*)(sm + SM_RUNS);
    const uint32_t hsm = smem_u32(sm);

    int tid  = threadIdx.x;
    int lane = tid & 31;
    int warp = tid >> 5;
    int q    = warp >> 2;            // quarter 0..3
    int w4   = warp & 3;
    int wm   = w4 >> 1;              // 0..1 (rows wm*64..+64)
    int wn   = w4 & 1;               // 0..1 (cols wn*32..+32 within 64-subtile)
    int qtid = tid & 127;
    const uint32_t wsm_q = hsm + SM_B + (uint32_t)q * (2 * QCHUNK);

    int bt = blockIdx.x;
    int b  = bt >> 8;
    const float* e_row = g_e + (size_t)bt * 640;
    const float* p_blk = g_p + (size_t)b * 128 * 640;
    float* out_blk = out + (size_t)bt * 128 * 1025;

    // preload own quarter's chunk 0 immediately (overlaps h build)
    issue_chunk(wsm_q, q, 0, qtid);
    asm volatile("cp.async.commit_group;\n" ::: "memory");

    // ---- build h = bf16(relu(e + p)) into smem, pitch 648 ----
#pragma unroll 4
    for (int it = 0; it < 40; it++) {
        int idx = (it * 512 + tid) * 4;
        int u = idx / 640, j = idx - u * 640;
        float4 pv = *(const float4*)(p_blk + (size_t)u * 640 + j);
        float4 ev = *(const float4*)(e_row + j);
        __nv_bfloat16* hp = hs + u * HP + j;
        *(__nv_bfloat162*)(hp)     = __floats2bfloat162_rn(fmaxf(ev.x + pv.x, 0.f),
                                                           fmaxf(ev.y + pv.y, 0.f));
        *(__nv_bfloat162*)(hp + 2) = __floats2bfloat162_rn(fmaxf(ev.z + pv.z, 0.f),
                                                           fmaxf(ev.w + pv.w, 0.f));
    }
    __syncthreads();

    // ---- column c = 1024 (scalar dot); init running stats
    //      (quarter 0 = real, quarters 1-3 = neutral) ----
    {
        int u = tid >> 2, qd = tid & 3;
        const uint4* hv4 = (const uint4*)(hs + u * HP + qd * 160);
        const uint4* wv4 = (const uint4*)(g_w + (size_t)1024 * 640 + qd * 160);
        float acc = 0.f;
#pragma unroll 4
        for (int it = 0; it < 20; it++) {
            uint4 hv = hv4[it];
            uint4 wv = wv4[it];
            const uint32_t* hu = (const uint32_t*)&hv;
            const uint32_t* wu = (const uint32_t*)&wv;
#pragma unroll
            for (int qq = 0; qq < 4; qq++) {
                float2 hf = __bfloat1622float2(*(const __nv_bfloat162*)&hu[qq]);
                float2 wf = __bfloat1622float2(*(const __nv_bfloat162*)&wu[qq]);
                acc += hf.x * wf.x + hf.y * wf.y;
            }
        }
        acc += __shfl_xor_sync(0xffffffffu, acc, 1);
        acc += __shfl_xor_sync(0xffffffffu, acc, 2);
        if (qd == 0) {
            float logit = acc + bout[1024];
            out_blk[(size_t)u * 1025 + 1024] = logit;
            runM[u] = logit;  runS[u] = 1.0f;              // quarter 0
#pragma unroll
            for (int z = 1; z < 4; z++) { runM[z * 128 + u] = -1e30f; runS[z * 128 + u] = 0.f; }
        }
    }
    __syncthreads();

    // ================= per-quarter independent pipeline =================
    int barid = 1 + q;

    // A-fragment double buffer, software-pipelined across chunk barriers.
    // Pattern: ks2 uses afr[ks2], loads afr[ks2^1] with the NEXT k-step.
    // A depends only on h (read-only), so crossing the W barrier is safe.
    uint32_t afr[2][4][4];
    {   // preload k-step 0 (kglob = 0)
        uint32_t ab = hsm + (uint32_t)((wm * 64 + (lane & 15)) * HP + (lane >> 4) * 8) * 2;
#pragma unroll
        for (int mi = 0; mi < 4; mi++) ldsm4(afr[0][mi], ab + mi * 16 * (HP * 2));
    }

    for (int nt = 0; nt < 4; nt++) {
        float acc[4][4][4];     // [mi][nj][frag]  64 regs
#pragma unroll
        for (int mi = 0; mi < 4; mi++)
#pragma unroll
            for (int nj = 0; nj < 4; nj++)
#pragma unroll
                for (int z = 0; z < 4; z++) acc[mi][nj][z] = 0.f;

        for (int kc = 0; kc < 20; kc++) {
            int g = nt * 20 + kc;
            asm volatile("cp.async.wait_group 0;\n" ::: "memory");
            bar_sync128(barid);
            if (g < 79) {
                issue_chunk(wsm_q, q, g + 1, qtid);
                asm volatile("cp.async.commit_group;\n" ::: "memory");
            }

            uint32_t wb = wsm_q + (uint32_t)(g & 1) * QCHUNK;
#pragma unroll
            for (int ks2 = 0; ks2 < 2; ks2++) {
                // B fragments for this ks2 (issued first: needed soonest)
                uint32_t bf[2][4];
                uint32_t bbase = wb +
                    (uint32_t)(wn * 32 + (lane & 7) + ((lane >> 4) << 3)) * 80 +
                    ks2 * 32 + ((lane >> 3) & 1) * 16;
                ldsm4(bf[0], bbase);
                ldsm4(bf[1], bbase + 16 * 80);

                // prefetch NEXT k-step's A fragments (hides under MMAs)
                {
                    int kn = (ks2 == 0) ? (kc * 32 + 16) : ((kc == 19) ? 0 : (kc + 1) * 32);
                    uint32_t ab = hsm +
                        (uint32_t)((wm * 64 + (lane & 15)) * HP + kn + (lane >> 4) * 8) * 2;
#pragma unroll
                    for (int mi = 0; mi < 4; mi++)
                        ldsm4(afr[ks2 ^ 1][mi], ab + mi * 16 * (HP * 2));
                }

#pragma unroll
                for (int mi = 0; mi < 4; mi++)
#pragma unroll
                    for (int nj = 0; nj < 4; nj++)
                        mma16816(acc[mi][nj], afr[ks2][mi], &bf[nj >> 1][(nj & 1) * 2]);
            }
        }

        // ---- epilogue: bias, per-row (max,sum) stats ----
        int cbase = q * 256 + nt * 64 + wn * 32;
#pragma unroll
        for (int mi = 0; mi < 4; mi++) {
#pragma unroll
            for (int nj = 0; nj < 4; nj++) {
                int c = cbase + nj * 8 + (lane & 3) * 2;
                float2 bb = *(const float2*)(bout + c);
                acc[mi][nj][0] += bb.x; acc[mi][nj][1] += bb.y;
                acc[mi][nj][2] += bb.x; acc[mi][nj][3] += bb.y;
            }
#pragma unroll
            for (int rh = 0; rh < 2; rh++) {
                float m = -1e30f;
#pragma unroll
                for (int nj = 0; nj < 4; nj++) {
                    m = fmaxf(m, acc[mi][nj][rh * 2]);
                    m = fmaxf(m, acc[mi][nj][rh * 2 + 1]);
                }
                m = fmaxf(m, __shfl_xor_sync(0xffffffffu, m, 1));
                m = fmaxf(m, __shfl_xor_sync(0xffffffffu, m, 2));
                float s = 0.f;
#pragma unroll
                for (int nj = 0; nj < 4; nj++) {
                    s += __expf(acc[mi][nj][rh * 2] - m);
                    s += __expf(acc[mi][nj][rh * 2 + 1] - m);
                }
                s += __shfl_xor_sync(0xffffffffu, s, 1);
                s += __shfl_xor_sync(0xffffffffu, s, 2);
                if ((lane & 3) == 0) {
                    int r = wm * 64 + mi * 16 + (lane >> 2) + rh * 8;
                    wmax[(q * 2 + wn) * 128 + r] = m;
                    wsum[(q * 2 + wn) * 128 + r] = s;
                }
            }
        }
        bar_sync128(barid);
        // merge the quarter's 2 n-warp-groups into its running stats
        {
            int u = qtid;
            float m0 = wmax[(q * 2) * 128 + u],     s0 = wsum[(q * 2) * 128 + u];
            float m1 = wmax[(q * 2 + 1) * 128 + u], s1 = wsum[(q * 2 + 1) * 128 + u];
            float nm = fmaxf(m0, m1);
            float ss = s0 * __expf(m0 - nm) + s1 * __expf(m1 - nm);
            float rm = runM[q * 128 + u], rs = runS[q * 128 + u];
            float nm2 = fmaxf(rm, nm);
            runS[q * 128 + u] = rs * __expf(rm - nm2) + ss * __expf(nm - nm2);
            runM[q * 128 + u] = nm2;
        }
        // (next nt's kc barriers order wmax reuse; no extra bar needed)

        // ---- direct logit stores from fragments (scalar, coalesced-ish) ----
#pragma unroll
        for (int mi = 0; mi < 4; mi++) {
            int r0 = wm * 64 + mi * 16 + (lane >> 2);
#pragma unroll
            for (int nj = 0; nj < 4; nj++) {
                int c = cbase + nj * 8 + (lane & 3) * 2;
                float* o0 = out_blk + (size_t)r0 * 1025 + c;
                o0[0] = acc[mi][nj][0]; o0[1] = acc[mi][nj][1];
                float* o1 = o0 + (size_t)8 * 1025;
                o1[0] = acc[mi][nj][2]; o1[1] = acc[mi][nj][3];
            }
        }
    }

    // ================= finalize =================
    __syncthreads();
    if (tid < 128) {
        float m = runM[tid], s = runS[tid];
#pragma unroll
        for (int z = 1; z < 4; z++) {
            float m2 = runM[z * 128 + tid], s2 = runS[z * 128 + tid];
            float nm = fmaxf(m, m2);
            s = s * __expf(m - nm) + s2 * __expf(m2 - nm);
            m = nm;
        }
        runM[tid] = m + logf(s);     // lse per row
    }
    __syncthreads();

    for (int i4 = tid; i4 < 32800; i4 += 512) {   // 128*1025/4, block base aligned
        float4* ptr = (float4*)out_blk + i4;
        float4 v = *ptr;
        int base = i4 * 4;
        v.x -= runM[base / 1025];
        v.y -= runM[(base + 1) / 1025];
        v.z -= runM[(base + 2) / 1025];
        v.w -= runM[(base + 3) / 1025];
        *ptr = v;
    }
}

// ---------------------------------------------------------------------------
extern "C" void kernel_launch(void* const* d_in, const int* in_sizes, int n_in,
                              void* d_out, int out_size) {
    const float* enc    = (const float*)d_in[0];
    const float* dec    = (const float*)d_in[1];
    const float* W_enc  = (const float*)d_in[2];
    const float* b_enc  = (const float*)d_in[3];
    const float* W_pred = (const float*)d_in[4];
    const float* b_pred = (const float*)d_in[5];
    const float* W_out  = (const float*)d_in[6];
    const float* b_out  = (const float*)d_in[7];
    float* out = (float*)d_out;

    convw_kernel<<<641, 256>>>(W_out);
    proj_kernel<<<dim3(16, 5), 256>>>(enc, W_enc, b_enc, E_, T_, 0);   // e
    proj_kernel<<<dim3(8, 5), 256>>>(dec, W_pred, b_pred, P_, U_, 1);  // p

    cudaFuncSetAttribute(joint_kernel,
                         cudaFuncAttributeMaxDynamicSharedMemorySize, SMEM_TOTAL);
    joint_kernel<<<2048, 512, SMEM_TOTAL>>>(b_out, out);
}